// round 2
// baseline (speedup 1.0000x reference)
#include <cuda_runtime.h>

typedef unsigned long long ull;

#define Bsz 64
#define Ssz 512
#define Dsz 256
#define Hsz 512
#define ROWS (Bsz * Ssz)   /* 32768 */
#define GXN  (4 * Hsz)     /* 2048  */
#define NBLK 128           /* persistent CTAs (<=148 SMs, all resident) */

// ---------------------------------------------------------------------------
// Static device scratch (no cudaMalloc allowed)
// ---------------------------------------------------------------------------
__device__ float g_gxq[(size_t)ROWS * GXN];   // 256 MB: [b*512+t][j*4+gate]
__device__ float g_hs[(size_t)ROWS * Hsz];    // 64 MB : [b*512+t][j]
__device__ float g_hbuf[2][Bsz * Hsz];        // double-buffered h
__device__ float g_c[Bsz * Hsz];              // final c
__device__ float g_Wq[Dsz * GXN];             // packed W: [d][j*4+gate]
__device__ float g_bq[GXN];                   // packed bias
__device__ unsigned g_count;
__device__ unsigned g_gen;

// ---------------------------------------------------------------------------
// f32x2 packed-math helpers (sm_100+ PTX; doubles FMA throughput per issue)
// ---------------------------------------------------------------------------
__device__ __forceinline__ ull fma2(ull a, ull b, ull c) {
    ull d; asm("fma.rn.f32x2 %0, %1, %2, %3;" : "=l"(d) : "l"(a), "l"(b), "l"(c)); return d;
}
__device__ __forceinline__ ull fadd2(ull a, ull b) {
    ull d; asm("add.rn.f32x2 %0, %1, %2;" : "=l"(d) : "l"(a), "l"(b)); return d;
}
__device__ __forceinline__ ull dup2(float x) {
    ull d; asm("mov.b64 %0, {%1, %1};" : "=l"(d) : "f"(x)); return d;
}
__device__ __forceinline__ float2 upk(ull a) {
    float2 r; asm("mov.b64 {%0, %1}, %2;" : "=f"(r.x), "=f"(r.y) : "l"(a)); return r;
}

__device__ __forceinline__ float sigmoidf_(float x) { return 1.0f / (1.0f + __expf(-x)); }
__device__ __forceinline__ float tanhf_(float x)    { return 1.0f - 2.0f / (__expf(2.0f * x) + 1.0f); }

// ---------------------------------------------------------------------------
// Kernel 0: reset barrier state + zero h0
// ---------------------------------------------------------------------------
__global__ void init_kernel() {
    int i = blockIdx.x * blockDim.x + threadIdx.x;   // 64 x 512 = 32768
    g_hbuf[0][i] = 0.0f;
    if (i == 0) { g_count = 0u; g_gen = 0u; }
}

// ---------------------------------------------------------------------------
// Kernel 1: pack W gates interleaved (f,i,o,c) per (d,j), and biases
// ---------------------------------------------------------------------------
__global__ void pack_kernel(const float* __restrict__ Wf, const float* __restrict__ Wi,
                            const float* __restrict__ Wo, const float* __restrict__ Wc,
                            const float* __restrict__ bf, const float* __restrict__ bi,
                            const float* __restrict__ bo, const float* __restrict__ bc) {
    int idx = blockIdx.x * blockDim.x + threadIdx.x;  // 512 x 256 = 131072 = Dsz*Hsz
    int d = idx >> 9;
    int j = idx & 511;
    float4 w;
    w.x = Wf[d * Hsz + j]; w.y = Wi[d * Hsz + j];
    w.z = Wo[d * Hsz + j]; w.w = Wc[d * Hsz + j];
    *(float4*)&g_Wq[(size_t)d * GXN + j * 4] = w;
    if (d == 0) {
        float4 b;
        b.x = bf[j]; b.y = bi[j]; b.z = bo[j]; b.w = bc[j];
        *(float4*)&g_bq[j * 4] = b;
    }
}

// ---------------------------------------------------------------------------
// Kernel 2: input-projection GEMM.  gxq[r][n] = x[r][:]·Wq[:][n] + bq[n]
//   M=32768, N=2048, K=256.  BM=BN=128, BK=16, 256 threads, TM=TN=8, FFMA2.
// ---------------------------------------------------------------------------
__global__ void __launch_bounds__(256, 2)
gemm_kernel(const float* __restrict__ A /* inputs flat [32768][256] */) {
    __shared__ float sA[128 * 20];   // [m][k], stride 20 (16B-aligned rows)
    __shared__ float sB[16 * 128];   // [k][n]

    const int tid = threadIdx.x;
    const int tx = tid & 15;         // n-dim
    const int ty = tid >> 4;         // m-dim
    const int r0 = blockIdx.y * 128;
    const int n0 = blockIdx.x * 128;

    ull acc[8][4];
    #pragma unroll
    for (int i = 0; i < 8; i++)
        #pragma unroll
        for (int p = 0; p < 4; p++) acc[i][p] = 0ull;

    for (int k0 = 0; k0 < Dsz; k0 += 16) {
        // load A tile: 128 x 16
        #pragma unroll
        for (int r = 0; r < 2; r++) {
            int v = r * 256 + tid;           // 0..511 float4s
            int mq = v >> 2, kq = v & 3;
            float4 f = *(const float4*)&A[(size_t)(r0 + mq) * Dsz + k0 + kq * 4];
            *(float4*)&sA[mq * 20 + kq * 4] = f;
        }
        // load B tile: 16 x 128 (from packed Wq)
        #pragma unroll
        for (int r = 0; r < 2; r++) {
            int v = r * 256 + tid;
            int kk = v >> 5, nq = v & 31;
            float4 f = *(const float4*)&g_Wq[(size_t)(k0 + kk) * GXN + n0 + nq * 4];
            *(float4*)&sB[kk * 128 + nq * 4] = f;
        }
        __syncthreads();

        #pragma unroll
        for (int kk = 0; kk < 16; kk++) {
            float av[8];
            #pragma unroll
            for (int i = 0; i < 8; i++) av[i] = sA[(ty * 8 + i) * 20 + kk];
            ulonglong2 b0 = *(const ulonglong2*)&sB[kk * 128 + tx * 8];
            ulonglong2 b1 = *(const ulonglong2*)&sB[kk * 128 + tx * 8 + 4];
            #pragma unroll
            for (int i = 0; i < 8; i++) {
                ull a2 = dup2(av[i]);
                acc[i][0] = fma2(b0.x, a2, acc[i][0]);
                acc[i][1] = fma2(b0.y, a2, acc[i][1]);
                acc[i][2] = fma2(b1.x, a2, acc[i][2]);
                acc[i][3] = fma2(b1.y, a2, acc[i][3]);
            }
        }
        __syncthreads();
    }

    // bias + store
    ulonglong2 bA = *(const ulonglong2*)&g_bq[n0 + tx * 8];
    ulonglong2 bB = *(const ulonglong2*)&g_bq[n0 + tx * 8 + 4];
    #pragma unroll
    for (int i = 0; i < 8; i++) {
        acc[i][0] = fadd2(acc[i][0], bA.x);
        acc[i][1] = fadd2(acc[i][1], bA.y);
        acc[i][2] = fadd2(acc[i][2], bB.x);
        acc[i][3] = fadd2(acc[i][3], bB.y);
        float* dst = &g_gxq[(size_t)(r0 + ty * 8 + i) * GXN + n0 + tx * 8];
        ulonglong2 s0; s0.x = acc[i][0]; s0.y = acc[i][1];
        ulonglong2 s1; s1.x = acc[i][2]; s1.y = acc[i][3];
        *(ulonglong2*)dst = s0;
        *(ulonglong2*)(dst + 4) = s1;
    }
}

// ---------------------------------------------------------------------------
// Kernel 3: persistent LSTM recurrence.
//   128 CTAs x 256 threads. CTA owns 4 j-columns (all gates), thread owns (b,j).
//   U slice in SMEM (32 KB, gate-interleaved float4), h chunk-staged in SMEM.
// ---------------------------------------------------------------------------
#define HCHUNK 128
#define HPAD   132   /* floats per b-row in smem (conflict-free, 16B-aligned) */

__global__ void __launch_bounds__(256, 1)
recur_kernel(const float* __restrict__ Uf, const float* __restrict__ Ui,
             const float* __restrict__ Uo, const float* __restrict__ Uc) {
    extern __shared__ char smem[];
    float* sU = (float*)smem;                      // 512k x 4jl x float4 = 32768 B
    float* sH = (float*)(smem + 32768);            // 64b x HPAD floats = 33792 B

    const int tid = threadIdx.x;
    const int b  = tid >> 2;
    const int jl = tid & 3;
    const int j  = blockIdx.x * 4 + jl;

    // Load this CTA's U slice once: sU[(k*4+jl)*4 + gate]
    for (int idx = tid; idx < Hsz * 4; idx += 256) {
        int k = idx >> 2, l = idx & 3;
        int gj = blockIdx.x * 4 + l;
        float4 u;
        u.x = Uf[(size_t)k * Hsz + gj]; u.y = Ui[(size_t)k * Hsz + gj];
        u.z = Uo[(size_t)k * Hsz + gj]; u.w = Uc[(size_t)k * Hsz + gj];
        *(float4*)&sU[(size_t)(k * 4 + l) * 4] = u;
    }
    __syncthreads();

    const ulonglong2* U2 = (const ulonglong2*)sU;  // index = k*4 + jl
    float cst = 0.0f;
    float4 pre[8];

    for (int t = 0; t < Ssz; t++) {
        const float* hp = g_hbuf[t & 1];

        // gate preactivations (gx part), pre-packed (f,i)/(o,c)
        ulonglong2 g2 = *(const ulonglong2*)&g_gxq[(size_t)(b * Ssz + t) * GXN + j * 4];
        ull afi = g2.x, aoc = g2.y;

        // prefetch chunk 0 of h (L2-only: L1 is stale across steps in a
        // persistent kernel)
        #pragma unroll
        for (int r = 0; r < 8; r++) {
            int v = r * 256 + tid;
            int bb = v >> 5, kq = v & 31;
            pre[r] = __ldcg((const float4*)&hp[bb * Hsz + kq * 4]);
        }

        for (int ch = 0; ch < Hsz / HCHUNK; ch++) {
            __syncthreads();                       // smem free from prev chunk
            #pragma unroll
            for (int r = 0; r < 8; r++) {
                int v = r * 256 + tid;
                int bb = v >> 5, kq = v & 31;
                *(float4*)&sH[bb * HPAD + kq * 4] = pre[r];
            }
            __syncthreads();
            if (ch < Hsz / HCHUNK - 1) {           // prefetch next chunk (overlaps compute)
                int kb = (ch + 1) * HCHUNK;
                #pragma unroll
                for (int r = 0; r < 8; r++) {
                    int v = r * 256 + tid;
                    int bb = v >> 5, kq = v & 31;
                    pre[r] = __ldcg((const float4*)&hp[bb * Hsz + kb + kq * 4]);
                }
            }
            const float4* hb4 = (const float4*)&sH[b * HPAD];
            const int kb = ch * HCHUNK;
            #pragma unroll
            for (int q = 0; q < HCHUNK / 4; q++) {
                float4 h4 = hb4[q];
                int k = kb + q * 4;
                ulonglong2 u0 = U2[(k + 0) * 4 + jl];
                ulonglong2 u1 = U2[(k + 1) * 4 + jl];
                ulonglong2 u2 = U2[(k + 2) * 4 + jl];
                ulonglong2 u3 = U2[(k + 3) * 4 + jl];
                ull hx = dup2(h4.x), hy = dup2(h4.y), hz = dup2(h4.z), hw = dup2(h4.w);
                afi = fma2(u0.x, hx, afi); aoc = fma2(u0.y, hx, aoc);
                afi = fma2(u1.x, hy, afi); aoc = fma2(u1.y, hy, aoc);
                afi = fma2(u2.x, hz, afi); aoc = fma2(u2.y, hz, aoc);
                afi = fma2(u3.x, hw, afi); aoc = fma2(u3.y, hw, aoc);
            }
        }

        // gates + state update
        float2 fi = upk(afi), oc = upk(aoc);
        float fg = sigmoidf_(fi.x);
        float ig = sigmoidf_(fi.y);
        float og = sigmoidf_(oc.x);
        float ch_ = tanhf_(oc.y);
        cst = fg * cst + ig * ch_;
        float hn = og * tanhf_(cst);

        g_hbuf[(t + 1) & 1][b * Hsz + j] = hn;
        g_hs[(size_t)(b * Ssz + t) * Hsz + j] = hn;

        // ---- grid barrier (sense = monotonically increasing generation) ----
        __threadfence();        // release our h stores to device scope
        __syncthreads();        // whole CTA done before arrival
        if (tid == 0) {
            unsigned target = (unsigned)NBLK * (unsigned)(t + 1);
            unsigned prev = atomicAdd(&g_count, 1u);
            if (prev + 1u == target) {
                atomicExch(&g_gen, (unsigned)(t + 1));
            } else {
                while (atomicAdd(&g_gen, 0u) < (unsigned)(t + 1)) { __nanosleep(64); }
            }
        }
        __syncthreads();
        __threadfence();        // acquire: other CTAs' h visible before next step
    }

    g_c[b * Hsz + j] = cst;
}

// ---------------------------------------------------------------------------
// Kernel 4: output head — pred[b][t] = hs[b][t][:]·Wfc + bfc  (1 warp / dot)
// ---------------------------------------------------------------------------
__global__ void head_kernel(const float* __restrict__ Wfc, const float* __restrict__ bfc,
                            float* __restrict__ out) {
    int warp = blockIdx.x * 8 + (threadIdx.x >> 5);  // 0..32767 == b*512+t
    int lane = threadIdx.x & 31;
    const float* hrow = &g_hs[(size_t)warp * Hsz];
    float acc = 0.0f;
    #pragma unroll
    for (int q = 0; q < 4; q++) {
        float4 h = *(const float4*)&hrow[q * 128 + lane * 4];
        float4 w = *(const float4*)&Wfc[q * 128 + lane * 4];
        acc += h.x * w.x + h.y * w.y + h.z * w.z + h.w * w.w;
    }
    #pragma unroll
    for (int s = 16; s > 0; s >>= 1) acc += __shfl_xor_sync(0xFFFFFFFFu, acc, s);
    if (lane == 0) out[warp] = acc + bfc[0];
}

// ---------------------------------------------------------------------------
// Kernel 5: copy h_t, c_t into output tail
// ---------------------------------------------------------------------------
__global__ void fin_kernel(float* __restrict__ out) {
    int i = blockIdx.x * blockDim.x + threadIdx.x;   // 0..32767
    out[32768 + i] = g_hbuf[0][i];                   // h after step 511 lives in buf 0
    out[65536 + i] = g_c[i];
}

// ---------------------------------------------------------------------------
extern "C" void kernel_launch(void* const* d_in, const int* in_sizes, int n_in,
                              void* d_out, int out_size) {
    const float* x   = (const float*)d_in[0];
    const float* Wf  = (const float*)d_in[1];
    const float* Wi  = (const float*)d_in[2];
    const float* Wo  = (const float*)d_in[3];
    const float* Wc  = (const float*)d_in[4];
    const float* bf  = (const float*)d_in[5];
    const float* bi  = (const float*)d_in[6];
    const float* bo  = (const float*)d_in[7];
    const float* bc  = (const float*)d_in[8];
    const float* Uf  = (const float*)d_in[9];
    const float* Ui  = (const float*)d_in[10];
    const float* Uo  = (const float*)d_in[11];
    const float* Uc  = (const float*)d_in[12];
    const float* Wfc = (const float*)d_in[13];
    const float* bfc = (const float*)d_in[14];
    float* out = (float*)d_out;

    static const int kRecurSmem = 32768 + Bsz * HPAD * 4;   // 66560 B
    cudaFuncSetAttribute(recur_kernel, cudaFuncAttributeMaxDynamicSharedMemorySize, kRecurSmem);

    init_kernel<<<64, 512>>>();
    pack_kernel<<<512, 256>>>(Wf, Wi, Wo, Wc, bf, bi, bo, bc);
    gemm_kernel<<<dim3(GXN / 128, ROWS / 128), 256>>>(x);
    recur_kernel<<<NBLK, 256, kRecurSmem>>>(Uf, Ui, Uo, Uc);
    head_kernel<<<ROWS / 8, 256>>>(Wfc, bfc, out);
    fin_kernel<<<64, 512>>>(out);
}

// round 5
// speedup vs baseline: 1.5833x; 1.5833x over previous
#include <cuda_runtime.h>

typedef unsigned long long ull;

#define Bsz 64
#define Ssz 512
#define Dsz 256
#define Hsz 512
#define ROWS (Bsz * Ssz)   /* 32768 */
#define GXN  (4 * Hsz)     /* 2048  */
#define NBLK 128           /* persistent CTAs (all resident on 148 SMs) */

// ---------------------------------------------------------------------------
// Static device scratch
// ---------------------------------------------------------------------------
__device__ float g_gxq[(size_t)ROWS * GXN];   // [b*512+t][j*4+gate]
__device__ float g_hs[(size_t)ROWS * Hsz];    // [b*512+t][j]
__device__ float g_hbuf[2][Bsz * Hsz];        // double-buffered h
__device__ float g_c[Bsz * Hsz];
__device__ float g_Wq[Dsz * GXN];             // packed W: [d][j*4+gate]
__device__ float g_bq[GXN];
// U packed for recurrence: ull pairs (U_g[2p][j], U_g[2p+1][j])
// layout: [jg(64)][p(256)][j8(8)][g(4)]  (ull)
__device__ ull g_Uq[64 * 256 * 8 * 4];
__device__ unsigned g_count;
__device__ unsigned g_gen;

// ---------------------------------------------------------------------------
// f32x2 helpers
// ---------------------------------------------------------------------------
__device__ __forceinline__ ull fma2(ull a, ull b, ull c) {
    ull d; asm("fma.rn.f32x2 %0, %1, %2, %3;" : "=l"(d) : "l"(a), "l"(b), "l"(c)); return d;
}
__device__ __forceinline__ ull fadd2(ull a, ull b) {
    ull d; asm("add.rn.f32x2 %0, %1, %2;" : "=l"(d) : "l"(a), "l"(b)); return d;
}
__device__ __forceinline__ ull dup2(float x) {
    ull d; asm("mov.b64 %0, {%1, %1};" : "=l"(d) : "f"(x)); return d;
}
__device__ __forceinline__ ull pk2(float lo, float hi) {
    ull d; asm("mov.b64 %0, {%1, %2};" : "=l"(d) : "f"(lo), "f"(hi)); return d;
}
__device__ __forceinline__ float2 upk(ull a) {
    float2 r; asm("mov.b64 {%0, %1}, %2;" : "=f"(r.x), "=f"(r.y) : "l"(a)); return r;
}
__device__ __forceinline__ unsigned ld_acq(const unsigned* p) {
    unsigned v; asm volatile("ld.acquire.gpu.b32 %0, [%1];" : "=r"(v) : "l"(p)); return v;
}

__device__ __forceinline__ float sigmoidf_(float x) { return 1.0f / (1.0f + __expf(-x)); }
__device__ __forceinline__ float tanhf_(float x)    { return 1.0f - 2.0f / (__expf(2.0f * x) + 1.0f); }

// ---------------------------------------------------------------------------
__global__ void init_kernel() {
    int i = blockIdx.x * blockDim.x + threadIdx.x;
    g_hbuf[0][i] = 0.0f;
    if (i == 0) { g_count = 0u; g_gen = 0u; }
}

// pack W gates interleaved (f,i,o,c) per (d,j), and biases
__global__ void pack_kernel(const float* __restrict__ Wf, const float* __restrict__ Wi,
                            const float* __restrict__ Wo, const float* __restrict__ Wc,
                            const float* __restrict__ bf, const float* __restrict__ bi,
                            const float* __restrict__ bo, const float* __restrict__ bc) {
    int idx = blockIdx.x * blockDim.x + threadIdx.x;  // Dsz*Hsz
    int d = idx >> 9;
    int j = idx & 511;
    float4 w;
    w.x = Wf[d * Hsz + j]; w.y = Wi[d * Hsz + j];
    w.z = Wo[d * Hsz + j]; w.w = Wc[d * Hsz + j];
    *(float4*)&g_Wq[(size_t)d * GXN + j * 4] = w;
    if (d == 0) {
        float4 b;
        b.x = bf[j]; b.y = bi[j]; b.z = bo[j]; b.w = bc[j];
        *(float4*)&g_bq[j * 4] = b;
    }
}

// pack U into k-pair ull layout [jg][p][j8][g]
__global__ void packu_kernel(const float* __restrict__ Uf, const float* __restrict__ Ui,
                             const float* __restrict__ Uo, const float* __restrict__ Uc) {
    int idx = blockIdx.x * blockDim.x + threadIdx.x;  // 256*512*4 = 524288
    int p = idx >> 11;
    int rem = idx & 2047;
    int j = rem >> 2;
    int g = rem & 3;
    const float* Ug = (g == 0) ? Uf : (g == 1) ? Ui : (g == 2) ? Uo : Uc;
    float lo = Ug[(size_t)(2 * p) * Hsz + j];
    float hi = Ug[(size_t)(2 * p + 1) * Hsz + j];
    int jg = j >> 3, j8 = j & 7;
    g_Uq[(((size_t)jg * 256 + p) * 8 + j8) * 4 + g] = pk2(lo, hi);
}

// ---------------------------------------------------------------------------
// input-projection GEMM (identical to the R2 passing kernel)
// ---------------------------------------------------------------------------
__global__ void __launch_bounds__(256, 2)
gemm_kernel(const float* __restrict__ A) {
    __shared__ float sA[128 * 20];
    __shared__ float sB[16 * 128];

    const int tid = threadIdx.x;
    const int tx = tid & 15;
    const int ty = tid >> 4;
    const int r0 = blockIdx.y * 128;
    const int n0 = blockIdx.x * 128;

    ull acc[8][4];
    #pragma unroll
    for (int i = 0; i < 8; i++)
        #pragma unroll
        for (int p = 0; p < 4; p++) acc[i][p] = 0ull;

    for (int k0 = 0; k0 < Dsz; k0 += 16) {
        #pragma unroll
        for (int r = 0; r < 2; r++) {
            int v = r * 256 + tid;
            int mq = v >> 2, kq = v & 3;
            float4 f = *(const float4*)&A[(size_t)(r0 + mq) * Dsz + k0 + kq * 4];
            *(float4*)&sA[mq * 20 + kq * 4] = f;
        }
        #pragma unroll
        for (int r = 0; r < 2; r++) {
            int v = r * 256 + tid;
            int kk = v >> 5, nq = v & 31;
            float4 f = *(const float4*)&g_Wq[(size_t)(k0 + kk) * GXN + n0 + nq * 4];
            *(float4*)&sB[kk * 128 + nq * 4] = f;
        }
        __syncthreads();

        #pragma unroll
        for (int kk = 0; kk < 16; kk++) {
            float av[8];
            #pragma unroll
            for (int i = 0; i < 8; i++) av[i] = sA[(ty * 8 + i) * 20 + kk];
            ulonglong2 b0 = *(const ulonglong2*)&sB[kk * 128 + tx * 8];
            ulonglong2 b1 = *(const ulonglong2*)&sB[kk * 128 + tx * 8 + 4];
            #pragma unroll
            for (int i = 0; i < 8; i++) {
                ull a2 = dup2(av[i]);
                acc[i][0] = fma2(b0.x, a2, acc[i][0]);
                acc[i][1] = fma2(b0.y, a2, acc[i][1]);
                acc[i][2] = fma2(b1.x, a2, acc[i][2]);
                acc[i][3] = fma2(b1.y, a2, acc[i][3]);
            }
        }
        __syncthreads();
    }

    ulonglong2 bA = *(const ulonglong2*)&g_bq[n0 + tx * 8];
    ulonglong2 bB = *(const ulonglong2*)&g_bq[n0 + tx * 8 + 4];
    #pragma unroll
    for (int i = 0; i < 8; i++) {
        acc[i][0] = fadd2(acc[i][0], bA.x);
        acc[i][1] = fadd2(acc[i][1], bA.y);
        acc[i][2] = fadd2(acc[i][2], bB.x);
        acc[i][3] = fadd2(acc[i][3], bB.y);
        float* dst = &g_gxq[(size_t)(r0 + ty * 8 + i) * GXN + n0 + tx * 8];
        ulonglong2 s0; s0.x = acc[i][0]; s0.y = acc[i][1];
        ulonglong2 s1; s1.x = acc[i][2]; s1.y = acc[i][3];
        *(ulonglong2*)dst = s0;
        *(ulonglong2*)(dst + 4) = s1;
    }
}

// ---------------------------------------------------------------------------
// persistent LSTM recurrence
//   128 CTAs = 64 jgroups x 2 bgroups. CTA: 8 j x 32 b, 512 threads.
//   thread: j8 = tid&7, bp = (tid>>3)&15, ks = tid>>7 (4-way k split)
//   cells: (b0 = bg*32+bp, j), (b1 = b0+16, j); k in [ks*128, ks*128+128)
//   SMEM: sU  256p x 8j8 x 48B (bank-perfect)  = 96 KB
//         sH  32 b-rows x 516 floats (padded)  = 66 KB
//         sRed 3 x 256 cells x float4          = 12 KB
// ---------------------------------------------------------------------------
#define SU_BYTES  (256 * 8 * 48)                 /* 98304 */
#define SH_OFF    SU_BYTES
#define SH_STRIDE 516
#define SH_BYTES  (32 * SH_STRIDE * 4)           /* 66048 */
#define SRED_OFF  (SH_OFF + SH_BYTES)            /* 164352 */
#define SRED_BYTES (3 * 256 * 16)                /* 12288 */
#define RECUR_SMEM (SRED_OFF + SRED_BYTES)       /* 176640 */

__global__ void __launch_bounds__(512, 1)
recur_kernel() {
    extern __shared__ char smem[];
    char*  sU   = smem;
    float* sH   = (float*)(smem + SH_OFF);
    float4* sRed = (float4*)(smem + SRED_OFF);

    const int tid = threadIdx.x;
    const int j8  = tid & 7;
    const int bp  = (tid >> 3) & 15;
    const int ks  = tid >> 7;
    const int jg  = blockIdx.x >> 1;
    const int bg  = blockIdx.x & 1;
    const int j   = jg * 8 + j8;
    const int b0g = bg * 32 + bp;
    const int b1g = b0g + 16;

    // ---- load U slice into bank-perfect padded SMEM (once) ----
    {
        const ull* uq = &g_Uq[(size_t)jg * 8192];
        for (int r = 0; r < 16; r++) {
            int v = r * 512 + tid;               // 0..8191 ull
            int p = v >> 5, jj = (v >> 2) & 7, g = v & 3;
            *(ull*)(sU + p * 384 + jj * 48 + g * 8) = uq[v];
        }
    }

    const char* uBase = sU + j8 * 48 + ks * 64 * 384;
    float c0 = 0.0f, c1 = 0.0f;

    for (int t = 0; t < Ssz; t++) {
        const float* hp = g_hbuf[t & 1];

        // gx prefetch for epilogue (ks==0 threads only)
        float4 gx0, gx1;
        if (ks == 0) {
            gx0 = *(const float4*)&g_gxq[(size_t)(b0g * Ssz + t) * GXN + j * 4];
            gx1 = *(const float4*)&g_gxq[(size_t)(b1g * Ssz + t) * GXN + j * 4];
        }

        // ---- stage h into SMEM (32 rows x 512, pad 516), L2-coherent ----
        #pragma unroll
        for (int r = 0; r < 8; r++) {
            int v = r * 512 + tid;               // float4 index 0..4095
            int row = v >> 7, c4 = v & 127;
            float4 f = __ldcg((const float4*)&hp[(bg * 32 + row) * Hsz + c4 * 4]);
            *(float4*)&sH[row * SH_STRIDE + c4 * 4] = f;
        }
        __syncthreads();

        // ---- main compute: 2 cells, 128-k window, pair-over-k FFMA2 ----
        ull aF0 = 0, aI0 = 0, aO0 = 0, aC0 = 0;
        ull aF1 = 0, aI1 = 0, aO1 = 0, aC1 = 0;
        {
            const ulonglong2* hA = (const ulonglong2*)&sH[bp * SH_STRIDE + ks * 128];
            const ulonglong2* hB = (const ulonglong2*)&sH[(bp + 16) * SH_STRIDE + ks * 128];
            const char* up = uBase;
            #pragma unroll 8
            for (int i = 0; i < 32; i++) {       // 4 k per iter (2 k-pairs)
                ulonglong2 ufi0 = *(const ulonglong2*)(up);
                ulonglong2 uoc0 = *(const ulonglong2*)(up + 16);
                ulonglong2 ufi1 = *(const ulonglong2*)(up + 384);
                ulonglong2 uoc1 = *(const ulonglong2*)(up + 400);
                ulonglong2 ha = hA[i];
                ulonglong2 hb = hB[i];
                aF0 = fma2(ufi0.x, ha.x, aF0);  aI0 = fma2(ufi0.y, ha.x, aI0);
                aO0 = fma2(uoc0.x, ha.x, aO0);  aC0 = fma2(uoc0.y, ha.x, aC0);
                aF1 = fma2(ufi0.x, hb.x, aF1);  aI1 = fma2(ufi0.y, hb.x, aI1);
                aO1 = fma2(uoc0.x, hb.x, aO1);  aC1 = fma2(uoc0.y, hb.x, aC1);
                aF0 = fma2(ufi1.x, ha.y, aF0);  aI0 = fma2(ufi1.y, ha.y, aI0);
                aO0 = fma2(uoc1.x, ha.y, aO0);  aC0 = fma2(uoc1.y, ha.y, aC0);
                aF1 = fma2(ufi1.x, hb.y, aF1);  aI1 = fma2(ufi1.y, hb.y, aI1);
                aO1 = fma2(uoc1.x, hb.y, aO1);  aC1 = fma2(uoc1.y, hb.y, aC1);
                up += 768;
            }
        }

        // fold f32x2 lanes -> scalars
        float2 t2;
        float4 p0, p1;
        t2 = upk(aF0); p0.x = t2.x + t2.y;   t2 = upk(aI0); p0.y = t2.x + t2.y;
        t2 = upk(aO0); p0.z = t2.x + t2.y;   t2 = upk(aC0); p0.w = t2.x + t2.y;
        t2 = upk(aF1); p1.x = t2.x + t2.y;   t2 = upk(aI1); p1.y = t2.x + t2.y;
        t2 = upk(aO1); p1.z = t2.x + t2.y;   t2 = upk(aC1); p1.w = t2.x + t2.y;

        int cell0 = bp * 8 + j8;                 // 0..127
        if (ks != 0) {
            sRed[(ks - 1) * 256 + cell0]       = p0;
            sRed[(ks - 1) * 256 + cell0 + 128] = p1;
        }
        __syncthreads();

        // ---- epilogue: ks==0 reduces, applies gates, writes h ----
        if (ks == 0) {
            float4 q0 = sRed[cell0],        q1 = sRed[256 + cell0],        q2 = sRed[512 + cell0];
            float4 r0_ = sRed[cell0 + 128], r1_ = sRed[256 + cell0 + 128], r2_ = sRed[512 + cell0 + 128];
            float pf0 = gx0.x + p0.x + q0.x + q1.x + q2.x;
            float pi0 = gx0.y + p0.y + q0.y + q1.y + q2.y;
            float po0 = gx0.z + p0.z + q0.z + q1.z + q2.z;
            float pc0 = gx0.w + p0.w + q0.w + q1.w + q2.w;
            float pf1 = gx1.x + p1.x + r0_.x + r1_.x + r2_.x;
            float pi1 = gx1.y + p1.y + r0_.y + r1_.y + r2_.y;
            float po1 = gx1.z + p1.z + r0_.z + r1_.z + r2_.z;
            float pc1 = gx1.w + p1.w + r0_.w + r1_.w + r2_.w;

            c0 = sigmoidf_(pf0) * c0 + sigmoidf_(pi0) * tanhf_(pc0);
            float h0 = sigmoidf_(po0) * tanhf_(c0);
            c1 = sigmoidf_(pf1) * c1 + sigmoidf_(pi1) * tanhf_(pc1);
            float h1 = sigmoidf_(po1) * tanhf_(c1);

            float* hn = g_hbuf[(t + 1) & 1];
            hn[b0g * Hsz + j] = h0;
            hn[b1g * Hsz + j] = h1;
            g_hs[(size_t)(b0g * Ssz + t) * Hsz + j] = h0;
            g_hs[(size_t)(b1g * Ssz + t) * Hsz + j] = h1;
        }

        // ---- grid barrier (bounded spin: fail-fast instead of device hang) ----
        __threadfence();
        __syncthreads();
        if (tid == 0) {
            unsigned target = (unsigned)NBLK * (unsigned)(t + 1);
            unsigned prev = atomicAdd(&g_count, 1u);
            if (prev + 1u == target) {
                atomicExch(&g_gen, (unsigned)(t + 1));
            } else {
                long long spins = 0;
                while (ld_acq(&g_gen) < (unsigned)(t + 1)) {
                    __nanosleep(64);
                    if (++spins > 100000000LL) break;   // ~unreachable; anti-wedge
                }
            }
        }
        __syncthreads();
    }

    if (ks == 0) {
        g_c[b0g * Hsz + j] = c0;
        g_c[b1g * Hsz + j] = c1;
    }
}

// ---------------------------------------------------------------------------
__global__ void head_kernel(const float* __restrict__ Wfc, const float* __restrict__ bfc,
                            float* __restrict__ out) {
    int warp = blockIdx.x * 8 + (threadIdx.x >> 5);
    int lane = threadIdx.x & 31;
    const float* hrow = &g_hs[(size_t)warp * Hsz];
    float acc = 0.0f;
    #pragma unroll
    for (int q = 0; q < 4; q++) {
        float4 h = *(const float4*)&hrow[q * 128 + lane * 4];
        float4 w = *(const float4*)&Wfc[q * 128 + lane * 4];
        acc += h.x * w.x + h.y * w.y + h.z * w.z + h.w * w.w;
    }
    #pragma unroll
    for (int s = 16; s > 0; s >>= 1) acc += __shfl_xor_sync(0xFFFFFFFFu, acc, s);
    if (lane == 0) out[warp] = acc + bfc[0];
}

__global__ void fin_kernel(float* __restrict__ out) {
    int i = blockIdx.x * blockDim.x + threadIdx.x;
    out[32768 + i] = g_hbuf[0][i];
    out[65536 + i] = g_c[i];
}

// ---------------------------------------------------------------------------
extern "C" void kernel_launch(void* const* d_in, const int* in_sizes, int n_in,
                              void* d_out, int out_size) {
    const float* x   = (const float*)d_in[0];
    const float* Wf  = (const float*)d_in[1];
    const float* Wi  = (const float*)d_in[2];
    const float* Wo  = (const float*)d_in[3];
    const float* Wc  = (const float*)d_in[4];
    const float* bf  = (const float*)d_in[5];
    const float* bi  = (const float*)d_in[6];
    const float* bo  = (const float*)d_in[7];
    const float* bc  = (const float*)d_in[8];
    const float* Uf  = (const float*)d_in[9];
    const float* Ui  = (const float*)d_in[10];
    const float* Uo  = (const float*)d_in[11];
    const float* Uc  = (const float*)d_in[12];
    const float* Wfc = (const float*)d_in[13];
    const float* bfc = (const float*)d_in[14];
    float* out = (float*)d_out;

    cudaFuncSetAttribute(recur_kernel, cudaFuncAttributeMaxDynamicSharedMemorySize, RECUR_SMEM);

    init_kernel<<<64, 512>>>();
    pack_kernel<<<512, 256>>>(Wf, Wi, Wo, Wc, bf, bi, bo, bc);
    packu_kernel<<<2048, 256>>>(Uf, Ui, Uo, Uc);
    gemm_kernel<<<dim3(GXN / 128, ROWS / 128), 256>>>(x);
    recur_kernel<<<NBLK, 512, RECUR_SMEM>>>();
    head_kernel<<<ROWS / 8, 256>>>(Wfc, bfc, out);
    fin_kernel<<<64, 512>>>(out);
}